// round 1
// baseline (speedup 1.0000x reference)
#include <cuda_runtime.h>
#include <math.h>

// Fixed problem shape: N = 128^3 points, 14 features, table 4 Mi entries.
#define N_MAX (128 * 128 * 128)

// Scratch for gf[0:3] (SoA) so pass2 reads it coalesced instead of
// re-gathering 3 random rows. 3 * 2M * 4B = 25 MB.
__device__ float  g_dm[3u * (unsigned)N_MAX];
__device__ double g_sum;
__device__ double g_sumsq;
__device__ float2 g_stats;   // x = mean, y = (2*far/vs/6)/std

__device__ __forceinline__ unsigned hash_idx(unsigned c0, unsigned c1, unsigned c2,
                                             unsigned tsize) {
    unsigned h = (c0 * 1u) ^ (c1 * 2654435761u) ^ (c2 * 805459861u);
    return h % tsize;
}

__device__ __forceinline__ float sigmoidf_(float x) {
    return 1.0f / (1.0f + expf(-x));
}

__global__ void k_init() {
    g_sum   = 0.0;
    g_sumsq = 0.0;
}

__global__ void k_pass1(const int* __restrict__ coords,
                        const float* __restrict__ table,
                        int n, unsigned tsize) {
    int i = blockIdx.x * blockDim.x + threadIdx.x;
    float s = 0.0f, ss = 0.0f;
    if (i < n) {
        unsigned c0 = (unsigned)coords[3 * i + 0];
        unsigned c1 = (unsigned)coords[3 * i + 1];
        unsigned c2 = (unsigned)coords[3 * i + 2];
        unsigned idx = hash_idx(c0, c1, c2, tsize);
        float g0 = __ldg(table + idx);
        float g1 = __ldg(table + (size_t)tsize + idx);
        float g2 = __ldg(table + 2 * (size_t)tsize + idx);
        g_dm[(size_t)i]                = g0;
        g_dm[(size_t)n + i]            = g1;
        g_dm[2 * (size_t)n + i]        = g2;
        s  = g0 + g1 + g2;
        ss = g0 * g0 + g1 * g1 + g2 * g2;
    }
    // warp reduce (float is fine: 96 values of ~N(0,1) per warp)
    #pragma unroll
    for (int o = 16; o > 0; o >>= 1) {
        s  += __shfl_down_sync(0xFFFFFFFFu, s,  o);
        ss += __shfl_down_sync(0xFFFFFFFFu, ss, o);
    }
    __shared__ double sh_s[8], sh_ss[8];
    int lane = threadIdx.x & 31;
    int w    = threadIdx.x >> 5;
    if (lane == 0) { sh_s[w] = (double)s; sh_ss[w] = (double)ss; }
    __syncthreads();
    if (threadIdx.x == 0) {
        double ts = 0.0, tss = 0.0;
        int nw = (blockDim.x + 31) >> 5;
        for (int j = 0; j < nw; j++) { ts += sh_s[j]; tss += sh_ss[j]; }
        atomicAdd(&g_sum, ts);
        atomicAdd(&g_sumsq, tss);
    }
}

__global__ void k_stats(const float* __restrict__ far_p,
                        const int* __restrict__ vs_p, int n) {
    double M    = 3.0 * (double)n;
    double mean = g_sum / M;
    double var  = (g_sumsq - g_sum * g_sum / M) / (M - 1.0);   // ddof = 1
    float stdv  = (float)sqrt(var);
    float f     = far_p[0];
    float vs    = (float)vs_p[0];
    float a     = 2.0f * f / vs;
    g_stats = make_float2((float)mean, a / (6.0f * stdv));
}

__global__ void k_main(const int* __restrict__ coords,
                       const float* __restrict__ table,
                       const float* __restrict__ cam,
                       const float* __restrict__ far_p,
                       const int* __restrict__ vs_p,
                       float* __restrict__ out,
                       int n, unsigned tsize) {
    int i = blockIdx.x * blockDim.x + threadIdx.x;
    if (i >= n) return;

    float f  = __ldg(far_p);
    float vs = (float)__ldg(vs_p);
    float a  = 2.0f * f / vs;          // 2*far/voxel_size
    float off = -f + f / vs;           // constant part of voxel_center
    float2 st = g_stats;               // mean, dm scale

    int c0 = coords[3 * i + 0];
    int c1 = coords[3 * i + 1];
    int c2 = coords[3 * i + 2];
    unsigned idx = hash_idx((unsigned)c0, (unsigned)c1, (unsigned)c2, tsize);

    // dm (rows 0-2) from coalesced scratch
    float dm0 = g_dm[(size_t)i];
    float dm1 = g_dm[(size_t)n + i];
    float dm2 = g_dm[2 * (size_t)n + i];

    // remaining 11 rows: random gathers
    const float* t = table;
    float q0 = __ldg(t + 3  * (size_t)tsize + idx);
    float q1 = __ldg(t + 4  * (size_t)tsize + idx);
    float q2 = __ldg(t + 5  * (size_t)tsize + idx);
    float q3 = __ldg(t + 6  * (size_t)tsize + idx);
    float s0 = __ldg(t + 7  * (size_t)tsize + idx);
    float s1 = __ldg(t + 8  * (size_t)tsize + idx);
    float s2 = __ldg(t + 9  * (size_t)tsize + idx);
    float h0 = __ldg(t + 10 * (size_t)tsize + idx);
    float h1 = __ldg(t + 11 * (size_t)tsize + idx);
    float h2 = __ldg(t + 12 * (size_t)tsize + idx);
    float op = __ldg(t + 13 * (size_t)tsize + idx);

    // means = (dm - mean)*scale + voxel_center
    float m0 = (dm0 - st.x) * st.y + (float)c0 * a + __ldg(cam + 0) + off;
    float m1 = (dm1 - st.x) * st.y + (float)c1 * a + __ldg(cam + 1) + off;
    float m2 = (dm2 - st.x) * st.y + (float)c2 * a + __ldg(cam + 2) + off;

    // quaternion -> rotation
    float rn = rsqrtf(q0 * q0 + q1 * q1 + q2 * q2 + q3 * q3);
    float r = q0 * rn, x = q1 * rn, y = q2 * rn, z = q3 * rn;
    float R00 = 1.0f - 2.0f * (y * y + z * z);
    float R01 = 2.0f * (x * y - r * z);
    float R02 = 2.0f * (x * z + r * y);
    float R10 = 2.0f * (x * y + r * z);
    float R11 = 1.0f - 2.0f * (x * x + z * z);
    float R12 = 2.0f * (y * z - r * x);
    float R20 = 2.0f * (x * z - r * y);
    float R21 = 2.0f * (y * z + r * x);
    float R22 = 1.0f - 2.0f * (x * x + y * y);

    // scales (per-column), covariance = (R * diag(s)) (R * diag(s))^T
    float sc0 = sigmoidf_(s0) * a;
    float sc1 = sigmoidf_(s1) * a;
    float sc2 = sigmoidf_(s2) * a;
    float v0 = sc0 * sc0, v1 = sc1 * sc1, v2 = sc2 * sc2;

    float cov00 = R00 * R00 * v0 + R01 * R01 * v1 + R02 * R02 * v2;
    float cov01 = R00 * R10 * v0 + R01 * R11 * v1 + R02 * R12 * v2;
    float cov02 = R00 * R20 * v0 + R01 * R21 * v1 + R02 * R22 * v2;
    float cov11 = R10 * R10 * v0 + R11 * R11 * v1 + R12 * R12 * v2;
    float cov12 = R10 * R20 * v0 + R11 * R21 * v1 + R12 * R22 * v2;
    float cov22 = R20 * R20 * v0 + R21 * R21 * v1 + R22 * R22 * v2;

    // output layout: means[3N] | cov[9N] | harmonics[3N] | opacities[N]
    float* means = out;
    float* cov   = out + 3  * (size_t)n;
    float* harm  = out + 12 * (size_t)n;
    float* opac  = out + 15 * (size_t)n;

    means[3 * (size_t)i + 0] = m0;
    means[3 * (size_t)i + 1] = m1;
    means[3 * (size_t)i + 2] = m2;

    size_t cb = 9 * (size_t)i;
    cov[cb + 0] = cov00; cov[cb + 1] = cov01; cov[cb + 2] = cov02;
    cov[cb + 3] = cov01; cov[cb + 4] = cov11; cov[cb + 5] = cov12;
    cov[cb + 6] = cov02; cov[cb + 7] = cov12; cov[cb + 8] = cov22;

    harm[3 * (size_t)i + 0] = h0;
    harm[3 * (size_t)i + 1] = h1;
    harm[3 * (size_t)i + 2] = h2;

    opac[i] = 1.0f / (1.0f + expf(4.0f - op));
}

extern "C" void kernel_launch(void* const* d_in, const int* in_sizes, int n_in,
                              void* d_out, int out_size) {
    const int*   coords = (const int*)d_in[0];
    const float* table  = (const float*)d_in[1];
    const float* cam    = (const float*)d_in[2];
    const float* far_p  = (const float*)d_in[3];
    const int*   vs_p   = (const int*)d_in[4];
    float*       out    = (float*)d_out;

    int n = in_sizes[0] / 3;
    unsigned tsize = (unsigned)(in_sizes[1] / 14);

    const int TPB = 256;
    int blocks = (n + TPB - 1) / TPB;

    k_init<<<1, 1>>>();
    k_pass1<<<blocks, TPB>>>(coords, table, n, tsize);
    k_stats<<<1, 1>>>(far_p, vs_p, n);
    k_main<<<blocks, TPB>>>(coords, table, cam, far_p, vs_p, out, n, tsize);
}

// round 2
// speedup vs baseline: 1.1458x; 1.1458x over previous
#include <cuda_runtime.h>
#include <math.h>

// Fixed problem shape: N = 128^3 points, 14 features, table 4 Mi entries.
#define N_MAX (128 * 128 * 128)

// Scratch (static device globals — no allocations).
__device__ unsigned g_idx[N_MAX];          // 8 MB  hash index per point
__device__ float    g_dm[3u * N_MAX];      // 25 MB rows 0-2 (SoA)
__device__ float    g_v [3u * N_MAX];      // 25 MB squared scaled sigmoids
__device__ double   g_sum;
__device__ double   g_sumsq;
__device__ float2   g_stats;               // x = mean, y = (2*far/vs/6)/std

__device__ __forceinline__ unsigned hash_idx(unsigned c0, unsigned c1, unsigned c2,
                                             unsigned tsize) {
    unsigned h = (c0 * 1u) ^ (c1 * 2654435761u) ^ (c2 * 805459861u);
    return h % tsize;
}

__device__ __forceinline__ float sigmoidf_(float x) {
    return 1.0f / (1.0f + expf(-x));
}

__global__ void k_init() {
    g_sum   = 0.0;
    g_sumsq = 0.0;
}

// Phase 1: rows 0-2 (working set 50 MB, fits L2). Hash once, stash idx + dm,
// reduce sum/sumsq for the global normalization.
__global__ void __launch_bounds__(256) k_pass1(const int* __restrict__ coords,
                                               const float* __restrict__ table,
                                               int n, unsigned tsize) {
    int i = blockIdx.x * blockDim.x + threadIdx.x;
    float s = 0.0f, ss = 0.0f;
    if (i < n) {
        unsigned c0 = (unsigned)coords[3 * i + 0];
        unsigned c1 = (unsigned)coords[3 * i + 1];
        unsigned c2 = (unsigned)coords[3 * i + 2];
        unsigned idx = hash_idx(c0, c1, c2, tsize);
        g_idx[i] = idx;
        float g0 = __ldg(table + idx);
        float g1 = __ldg(table + (size_t)tsize + idx);
        float g2 = __ldg(table + 2 * (size_t)tsize + idx);
        g_dm[(size_t)i]         = g0;
        g_dm[(size_t)n + i]     = g1;
        g_dm[2 * (size_t)n + i] = g2;
        s  = g0 + g1 + g2;
        ss = g0 * g0 + g1 * g1 + g2 * g2;
    }
    #pragma unroll
    for (int o = 16; o > 0; o >>= 1) {
        s  += __shfl_down_sync(0xFFFFFFFFu, s,  o);
        ss += __shfl_down_sync(0xFFFFFFFFu, ss, o);
    }
    __shared__ double sh_s[8], sh_ss[8];
    int lane = threadIdx.x & 31;
    int w    = threadIdx.x >> 5;
    if (lane == 0) { sh_s[w] = (double)s; sh_ss[w] = (double)ss; }
    __syncthreads();
    if (threadIdx.x == 0) {
        double ts = 0.0, tss = 0.0;
        int nw = (blockDim.x + 31) >> 5;
        for (int j = 0; j < nw; j++) { ts += sh_s[j]; tss += sh_ss[j]; }
        atomicAdd(&g_sum, ts);
        atomicAdd(&g_sumsq, tss);
    }
}

__global__ void k_stats(const float* __restrict__ far_p,
                        const int* __restrict__ vs_p, int n) {
    double M    = 3.0 * (double)n;
    double mean = g_sum / M;
    double var  = (g_sumsq - g_sum * g_sum / M) / (M - 1.0);   // ddof = 1
    float stdv  = (float)sqrt(var);
    float f     = far_p[0];
    float vs    = (float)vs_p[0];
    float a     = 2.0f * f / vs;
    g_stats = make_float2((float)mean, a / (6.0f * stdv));
}

// Phase 2: rows 7-9 (50 MB). v = (sigmoid(s) * 2*far/vs)^2, stashed SoA.
__global__ void __launch_bounds__(256) k_scales(const float* __restrict__ table,
                                                const float* __restrict__ far_p,
                                                const int* __restrict__ vs_p,
                                                int n, unsigned tsize) {
    int i = blockIdx.x * blockDim.x + threadIdx.x;
    if (i >= n) return;
    float f  = __ldg(far_p);
    float vs = (float)__ldg(vs_p);
    float a  = 2.0f * f / vs;
    unsigned idx = g_idx[i];
    float s0 = __ldg(table + 7 * (size_t)tsize + idx);
    float s1 = __ldg(table + 8 * (size_t)tsize + idx);
    float s2 = __ldg(table + 9 * (size_t)tsize + idx);
    float sc0 = sigmoidf_(s0) * a;
    float sc1 = sigmoidf_(s1) * a;
    float sc2 = sigmoidf_(s2) * a;
    g_v[(size_t)i]         = sc0 * sc0;
    g_v[(size_t)n + i]     = sc1 * sc1;
    g_v[2 * (size_t)n + i] = sc2 * sc2;
}

// Phase 3: rows 3-6 (67 MB). Quaternion -> R, covariance = R diag(v) R^T.
// Stores staged through smem so the 36B-stride cov writes go out coalesced.
__global__ void __launch_bounds__(256) k_quat(const float* __restrict__ table,
                                              float* __restrict__ out,
                                              int n, unsigned tsize) {
    __shared__ float sh[256 * 9];
    int i = blockIdx.x * blockDim.x + threadIdx.x;
    int t = threadIdx.x;
    if (i < n) {
        unsigned idx = g_idx[i];
        float q0 = __ldg(table + 3 * (size_t)tsize + idx);
        float q1 = __ldg(table + 4 * (size_t)tsize + idx);
        float q2 = __ldg(table + 5 * (size_t)tsize + idx);
        float q3 = __ldg(table + 6 * (size_t)tsize + idx);

        float rn = rsqrtf(q0 * q0 + q1 * q1 + q2 * q2 + q3 * q3);
        float r = q0 * rn, x = q1 * rn, y = q2 * rn, z = q3 * rn;
        float R00 = 1.0f - 2.0f * (y * y + z * z);
        float R01 = 2.0f * (x * y - r * z);
        float R02 = 2.0f * (x * z + r * y);
        float R10 = 2.0f * (x * y + r * z);
        float R11 = 1.0f - 2.0f * (x * x + z * z);
        float R12 = 2.0f * (y * z - r * x);
        float R20 = 2.0f * (x * z - r * y);
        float R21 = 2.0f * (y * z + r * x);
        float R22 = 1.0f - 2.0f * (x * x + y * y);

        float v0 = g_v[(size_t)i];
        float v1 = g_v[(size_t)n + i];
        float v2 = g_v[2 * (size_t)n + i];

        float c00 = R00 * R00 * v0 + R01 * R01 * v1 + R02 * R02 * v2;
        float c01 = R00 * R10 * v0 + R01 * R11 * v1 + R02 * R12 * v2;
        float c02 = R00 * R20 * v0 + R01 * R21 * v1 + R02 * R22 * v2;
        float c11 = R10 * R10 * v0 + R11 * R11 * v1 + R12 * R12 * v2;
        float c12 = R10 * R20 * v0 + R11 * R21 * v1 + R12 * R22 * v2;
        float c22 = R20 * R20 * v0 + R21 * R21 * v1 + R22 * R22 * v2;

        float* p = sh + t * 9;
        p[0] = c00; p[1] = c01; p[2] = c02;
        p[3] = c01; p[4] = c11; p[5] = c12;
        p[6] = c02; p[7] = c12; p[8] = c22;
    }
    __syncthreads();
    // coalesced streaming copy of this block's cov slab
    float* cov = out + 3 * (size_t)n;
    size_t base = (size_t)blockIdx.x * blockDim.x * 9;
    int cnt = min((int)blockDim.x, n - blockIdx.x * (int)blockDim.x) * 9;
    for (int k = t; k < cnt; k += blockDim.x)
        __stcs(cov + base + k, sh[k]);
}

// Phase 4: rows 10-13 (67 MB) + stashed dm -> means, harmonics, opacities.
__global__ void __launch_bounds__(256) k_rest(const int* __restrict__ coords,
                                              const float* __restrict__ table,
                                              const float* __restrict__ cam,
                                              const float* __restrict__ far_p,
                                              const int* __restrict__ vs_p,
                                              float* __restrict__ out,
                                              int n, unsigned tsize) {
    __shared__ float sh_m[256 * 3];
    __shared__ float sh_h[256 * 3];
    int i = blockIdx.x * blockDim.x + threadIdx.x;
    int t = threadIdx.x;
    float op = 0.0f;
    if (i < n) {
        float f  = __ldg(far_p);
        float vs = (float)__ldg(vs_p);
        float a  = 2.0f * f / vs;
        float off = -f + f / vs;
        float2 st = g_stats;

        unsigned idx = g_idx[i];
        float h0  = __ldg(table + 10 * (size_t)tsize + idx);
        float h1  = __ldg(table + 11 * (size_t)tsize + idx);
        float h2  = __ldg(table + 12 * (size_t)tsize + idx);
        float opr = __ldg(table + 13 * (size_t)tsize + idx);

        int c0 = coords[3 * i + 0];
        int c1 = coords[3 * i + 1];
        int c2 = coords[3 * i + 2];

        float dm0 = g_dm[(size_t)i];
        float dm1 = g_dm[(size_t)n + i];
        float dm2 = g_dm[2 * (size_t)n + i];

        sh_m[t * 3 + 0] = (dm0 - st.x) * st.y + (float)c0 * a + __ldg(cam + 0) + off;
        sh_m[t * 3 + 1] = (dm1 - st.x) * st.y + (float)c1 * a + __ldg(cam + 1) + off;
        sh_m[t * 3 + 2] = (dm2 - st.x) * st.y + (float)c2 * a + __ldg(cam + 2) + off;
        sh_h[t * 3 + 0] = h0;
        sh_h[t * 3 + 1] = h1;
        sh_h[t * 3 + 2] = h2;
        op = 1.0f / (1.0f + expf(4.0f - opr));
    }
    __syncthreads();
    float* means = out;
    float* harm  = out + 12 * (size_t)n;
    float* opac  = out + 15 * (size_t)n;
    size_t base = (size_t)blockIdx.x * blockDim.x * 3;
    int cnt = min((int)blockDim.x, n - blockIdx.x * (int)blockDim.x) * 3;
    for (int k = t; k < cnt; k += blockDim.x) {
        __stcs(means + base + k, sh_m[k]);
        __stcs(harm  + base + k, sh_h[k]);
    }
    if (i < n) __stcs(opac + i, op);
}

extern "C" void kernel_launch(void* const* d_in, const int* in_sizes, int n_in,
                              void* d_out, int out_size) {
    const int*   coords = (const int*)d_in[0];
    const float* table  = (const float*)d_in[1];
    const float* cam    = (const float*)d_in[2];
    const float* far_p  = (const float*)d_in[3];
    const int*   vs_p   = (const int*)d_in[4];
    float*       out    = (float*)d_out;

    int n = in_sizes[0] / 3;
    unsigned tsize = (unsigned)(in_sizes[1] / 14);

    const int TPB = 256;
    int blocks = (n + TPB - 1) / TPB;

    k_init  <<<1, 1>>>();
    k_pass1 <<<blocks, TPB>>>(coords, table, n, tsize);
    k_stats <<<1, 1>>>(far_p, vs_p, n);
    k_scales<<<blocks, TPB>>>(table, far_p, vs_p, n, tsize);
    k_quat  <<<blocks, TPB>>>(table, out, n, tsize);
    k_rest  <<<blocks, TPB>>>(coords, table, cam, far_p, vs_p, out, n, tsize);
}

// round 3
// speedup vs baseline: 1.2292x; 1.0728x over previous
#include <cuda_runtime.h>
#include <math.h>

#define N_MAX (128 * 128 * 128)
#define TPB 256
#define PPB 512   // points per block (2 per thread)

__device__ unsigned g_idx[N_MAX];          // 8 MB  hash index per point
__device__ float    g_dm[3u * N_MAX];      // 25 MB rows 0-2 (SoA)
__device__ double   g_sum;
__device__ double   g_sumsq;
__device__ float2   g_stats;               // x = mean, y = (2*far/vs/6)/std

__device__ __forceinline__ unsigned hash_idx(unsigned c0, unsigned c1, unsigned c2,
                                             unsigned tsize) {
    unsigned h = (c0 * 1u) ^ (c1 * 2654435761u) ^ (c2 * 805459861u);
    return h % tsize;
}

__device__ __forceinline__ float sigmoidf_(float x) {
    return 1.0f / (1.0f + expf(-x));
}

__global__ void k_init() {
    g_sum   = 0.0;
    g_sumsq = 0.0;
}

// Phase 1: rows 0-2 (WS 50 MB). Hash once, stash idx + dm, reduce stats.
__global__ void __launch_bounds__(TPB) k_pass1(const int* __restrict__ coords,
                                               const float* __restrict__ table,
                                               int n, unsigned tsize) {
    int t  = threadIdx.x;
    int i0 = blockIdx.x * PPB + t;
    int i1 = i0 + TPB;
    float s = 0.0f, ss = 0.0f;

    #pragma unroll
    for (int k = 0; k < 2; k++) {
        int i = (k == 0) ? i0 : i1;
        if (i < n) {
            unsigned c0 = (unsigned)coords[3 * i + 0];
            unsigned c1 = (unsigned)coords[3 * i + 1];
            unsigned c2 = (unsigned)coords[3 * i + 2];
            unsigned idx = hash_idx(c0, c1, c2, tsize);
            g_idx[i] = idx;
            float g0 = __ldg(table + idx);
            float g1 = __ldg(table + (size_t)tsize + idx);
            float g2 = __ldg(table + 2 * (size_t)tsize + idx);
            g_dm[(size_t)i]         = g0;
            g_dm[(size_t)n + i]     = g1;
            g_dm[2 * (size_t)n + i] = g2;
            s  += g0 + g1 + g2;
            ss += g0 * g0 + g1 * g1 + g2 * g2;
        }
    }
    #pragma unroll
    for (int o = 16; o > 0; o >>= 1) {
        s  += __shfl_down_sync(0xFFFFFFFFu, s,  o);
        ss += __shfl_down_sync(0xFFFFFFFFu, ss, o);
    }
    __shared__ double sh_s[8], sh_ss[8];
    int lane = t & 31, w = t >> 5;
    if (lane == 0) { sh_s[w] = (double)s; sh_ss[w] = (double)ss; }
    __syncthreads();
    if (t == 0) {
        double ts = 0.0, tss = 0.0;
        for (int j = 0; j < TPB / 32; j++) { ts += sh_s[j]; tss += sh_ss[j]; }
        atomicAdd(&g_sum, ts);
        atomicAdd(&g_sumsq, tss);
    }
}

__global__ void k_stats(const float* __restrict__ far_p,
                        const int* __restrict__ vs_p, int n) {
    double M    = 3.0 * (double)n;
    double mean = g_sum / M;
    double var  = (g_sumsq - g_sum * g_sum / M) / (M - 1.0);   // ddof = 1
    float stdv  = (float)sqrt(var);
    float f     = far_p[0];
    float vs    = (float)vs_p[0];
    float a     = 2.0f * f / vs;
    g_stats = make_float2((float)mean, a / (6.0f * stdv));
}

// Phase 2: rows 3-9 fused (WS 117 MB). quat + scales -> covariance.
__global__ void __launch_bounds__(TPB) k_cov(const float* __restrict__ table,
                                             const float* __restrict__ far_p,
                                             const int* __restrict__ vs_p,
                                             float* __restrict__ out,
                                             int n, unsigned tsize) {
    __shared__ __align__(16) float sh[PPB * 9];
    int t  = threadIdx.x;
    int i0 = blockIdx.x * PPB + t;

    float f  = __ldg(far_p);
    float vs = (float)__ldg(vs_p);
    float a  = 2.0f * f / vs;

    unsigned idxA = (i0       < n) ? g_idx[i0]       : 0u;
    unsigned idxB = (i0 + TPB < n) ? g_idx[i0 + TPB] : 0u;

    // issue all 14 gathers up front (max MLP)
    const float* t3 = table + 3 * (size_t)tsize;
    const float* t4 = table + 4 * (size_t)tsize;
    const float* t5 = table + 5 * (size_t)tsize;
    const float* t6 = table + 6 * (size_t)tsize;
    const float* t7 = table + 7 * (size_t)tsize;
    const float* t8 = table + 8 * (size_t)tsize;
    const float* t9 = table + 9 * (size_t)tsize;

    float qA0 = __ldg(t3 + idxA), qB0 = __ldg(t3 + idxB);
    float qA1 = __ldg(t4 + idxA), qB1 = __ldg(t4 + idxB);
    float qA2 = __ldg(t5 + idxA), qB2 = __ldg(t5 + idxB);
    float qA3 = __ldg(t6 + idxA), qB3 = __ldg(t6 + idxB);
    float sA0 = __ldg(t7 + idxA), sB0 = __ldg(t7 + idxB);
    float sA1 = __ldg(t8 + idxA), sB1 = __ldg(t8 + idxB);
    float sA2 = __ldg(t9 + idxA), sB2 = __ldg(t9 + idxB);

    #pragma unroll
    for (int k = 0; k < 2; k++) {
        float q0 = k ? qB0 : qA0, q1 = k ? qB1 : qA1;
        float q2 = k ? qB2 : qA2, q3 = k ? qB3 : qA3;
        float s0 = k ? sB0 : sA0, s1 = k ? sB1 : sA1, s2 = k ? sB2 : sA2;

        float rn = rsqrtf(q0 * q0 + q1 * q1 + q2 * q2 + q3 * q3);
        float r = q0 * rn, x = q1 * rn, y = q2 * rn, z = q3 * rn;
        float R00 = 1.0f - 2.0f * (y * y + z * z);
        float R01 = 2.0f * (x * y - r * z);
        float R02 = 2.0f * (x * z + r * y);
        float R10 = 2.0f * (x * y + r * z);
        float R11 = 1.0f - 2.0f * (x * x + z * z);
        float R12 = 2.0f * (y * z - r * x);
        float R20 = 2.0f * (x * z - r * y);
        float R21 = 2.0f * (y * z + r * x);
        float R22 = 1.0f - 2.0f * (x * x + y * y);

        float sc0 = sigmoidf_(s0) * a;
        float sc1 = sigmoidf_(s1) * a;
        float sc2 = sigmoidf_(s2) * a;
        float v0 = sc0 * sc0, v1 = sc1 * sc1, v2 = sc2 * sc2;

        float c00 = R00 * R00 * v0 + R01 * R01 * v1 + R02 * R02 * v2;
        float c01 = R00 * R10 * v0 + R01 * R11 * v1 + R02 * R12 * v2;
        float c02 = R00 * R20 * v0 + R01 * R21 * v1 + R02 * R22 * v2;
        float c11 = R10 * R10 * v0 + R11 * R11 * v1 + R12 * R12 * v2;
        float c12 = R10 * R20 * v0 + R11 * R21 * v1 + R12 * R22 * v2;
        float c22 = R20 * R20 * v0 + R21 * R21 * v1 + R22 * R22 * v2;

        float* p = sh + (t + k * TPB) * 9;
        p[0] = c00; p[1] = c01; p[2] = c02;
        p[3] = c01; p[4] = c11; p[5] = c12;
        p[6] = c02; p[7] = c12; p[8] = c22;
    }
    __syncthreads();

    float* cov = out + 3 * (size_t)n;
    int blk_pts = min(PPB, n - blockIdx.x * PPB);
    size_t base = (size_t)blockIdx.x * PPB * 9;
    if (blk_pts == PPB) {
        // 4608 floats = 1152 float4, coalesced streaming
        const float4* s4 = (const float4*)sh;
        float4* d4 = (float4*)(cov + base);
        for (int k = t; k < PPB * 9 / 4; k += TPB)
            __stcs(d4 + k, s4[k]);
    } else {
        int cnt = blk_pts * 9;
        for (int k = t; k < cnt; k += TPB)
            __stcs(cov + base + k, sh[k]);
    }
}

// Phase 3: rows 10-13 (WS 67 MB) + stashed dm -> means, harmonics, opacities.
__global__ void __launch_bounds__(TPB) k_rest(const int* __restrict__ coords,
                                              const float* __restrict__ table,
                                              const float* __restrict__ cam,
                                              const float* __restrict__ far_p,
                                              const int* __restrict__ vs_p,
                                              float* __restrict__ out,
                                              int n, unsigned tsize) {
    __shared__ __align__(16) float sh_m[PPB * 3];
    __shared__ __align__(16) float sh_h[PPB * 3];
    int t  = threadIdx.x;
    int i0 = blockIdx.x * PPB + t;

    float f  = __ldg(far_p);
    float vs = (float)__ldg(vs_p);
    float a  = 2.0f * f / vs;
    float off = -f + f / vs;
    float2 st = g_stats;
    float cm0 = __ldg(cam + 0), cm1 = __ldg(cam + 1), cm2 = __ldg(cam + 2);

    const float* t10 = table + 10 * (size_t)tsize;
    const float* t11 = table + 11 * (size_t)tsize;
    const float* t12 = table + 12 * (size_t)tsize;
    const float* t13 = table + 13 * (size_t)tsize;

    unsigned idxA = (i0       < n) ? g_idx[i0]       : 0u;
    unsigned idxB = (i0 + TPB < n) ? g_idx[i0 + TPB] : 0u;

    float hA0 = __ldg(t10 + idxA), hB0 = __ldg(t10 + idxB);
    float hA1 = __ldg(t11 + idxA), hB1 = __ldg(t11 + idxB);
    float hA2 = __ldg(t12 + idxA), hB2 = __ldg(t12 + idxB);
    float oA  = __ldg(t13 + idxA), oB  = __ldg(t13 + idxB);

    float opOut[2] = {0.0f, 0.0f};
    #pragma unroll
    for (int k = 0; k < 2; k++) {
        int i = i0 + k * TPB;
        if (i < n) {
            int c0 = coords[3 * i + 0];
            int c1 = coords[3 * i + 1];
            int c2 = coords[3 * i + 2];
            float dm0 = g_dm[(size_t)i];
            float dm1 = g_dm[(size_t)n + i];
            float dm2 = g_dm[2 * (size_t)n + i];
            int ts_ = t + k * TPB;
            sh_m[ts_ * 3 + 0] = (dm0 - st.x) * st.y + (float)c0 * a + cm0 + off;
            sh_m[ts_ * 3 + 1] = (dm1 - st.x) * st.y + (float)c1 * a + cm1 + off;
            sh_m[ts_ * 3 + 2] = (dm2 - st.x) * st.y + (float)c2 * a + cm2 + off;
            sh_h[ts_ * 3 + 0] = k ? hB0 : hA0;
            sh_h[ts_ * 3 + 1] = k ? hB1 : hA1;
            sh_h[ts_ * 3 + 2] = k ? hB2 : hA2;
            opOut[k] = 1.0f / (1.0f + expf(4.0f - (k ? oB : oA)));
        }
    }
    __syncthreads();

    float* means = out;
    float* harm  = out + 12 * (size_t)n;
    float* opac  = out + 15 * (size_t)n;
    int blk_pts = min(PPB, n - blockIdx.x * PPB);
    size_t base = (size_t)blockIdx.x * PPB * 3;
    if (blk_pts == PPB) {
        const float4* sm4 = (const float4*)sh_m;
        const float4* sh4 = (const float4*)sh_h;
        float4* dm4 = (float4*)(means + base);
        float4* dh4 = (float4*)(harm + base);
        for (int k = t; k < PPB * 3 / 4; k += TPB) {
            __stcs(dm4 + k, sm4[k]);
            __stcs(dh4 + k, sh4[k]);
        }
    } else {
        int cnt = blk_pts * 3;
        for (int k = t; k < cnt; k += TPB) {
            __stcs(means + base + k, sh_m[k]);
            __stcs(harm  + base + k, sh_h[k]);
        }
    }
    if (i0 < n)       __stcs(opac + i0,       opOut[0]);
    if (i0 + TPB < n) __stcs(opac + i0 + TPB, opOut[1]);
}

extern "C" void kernel_launch(void* const* d_in, const int* in_sizes, int n_in,
                              void* d_out, int out_size) {
    const int*   coords = (const int*)d_in[0];
    const float* table  = (const float*)d_in[1];
    const float* cam    = (const float*)d_in[2];
    const float* far_p  = (const float*)d_in[3];
    const int*   vs_p   = (const int*)d_in[4];
    float*       out    = (float*)d_out;

    int n = in_sizes[0] / 3;
    unsigned tsize = (unsigned)(in_sizes[1] / 14);

    int blocks = (n + PPB - 1) / PPB;

    k_init <<<1, 1>>>();
    k_pass1<<<blocks, TPB>>>(coords, table, n, tsize);
    k_stats<<<1, 1>>>(far_p, vs_p, n);
    k_cov  <<<blocks, TPB>>>(table, far_p, vs_p, out, n, tsize);
    k_rest <<<blocks, TPB>>>(coords, table, cam, far_p, vs_p, out, n, tsize);
}